// round 7
// baseline (speedup 1.0000x reference)
#include <cuda_runtime.h>
#include <cuda_bf16.h>
#include <cstdint>

#define NN 100000
#define NE 3200000
#define NG 256
#define NF 64

// -------- scratch (no allocations allowed) --------
__device__ float  g_deg[NN];
__device__ float  g_dinv[NN];
__device__ float  g_p[NN];            // x * dinv (normalized source scalar, layer 1)
__device__ float  g_a[NN];            // scalar accumulator, layer 1
__device__ float4 g_s[NN * 16];       // s1 = (h1 @ W2) * dinv  [N,64]
__device__ float4 g_acc[NN * 16];     // layer-2 accumulator    [N,64]
__device__ float  g_gsum[NG * NF];
__device__ float  g_gcnt[NG];

__device__ __forceinline__ float gelu_t(float x) {
    const float c = 0.7978845608028654f;
    float t = tanhf(c * (x + 0.044715f * x * x * x));
    return 0.5f * x * (1.0f + t);
}

__device__ __forceinline__ void red_add_v4(float4* addr, float4 v) {
    asm volatile("red.global.add.v4.f32 [%0], {%1,%2,%3,%4};"
                 :: "l"(addr), "f"(v.x), "f"(v.y), "f"(v.z), "f"(v.w)
                 : "memory");
}

// K0: init deg=1 (self loop), zero pool buffers
__global__ void k0_init() {
    int i = blockIdx.x * blockDim.x + threadIdx.x;
    if (i < NN) g_deg[i] = 1.0f;
    if (i < NG * NF) g_gsum[i] = 0.0f;
    if (i < NG) g_gcnt[i] = 0.0f;
}

// K1: deg[col] += ew
__global__ void __launch_bounds__(256) k1_deg(const int* __restrict__ ei,
                                              const float* __restrict__ ew) {
    int e = blockIdx.x * blockDim.x + threadIdx.x;
    if (e >= NE) return;
    int c = __ldg(&ei[NE + e]);
    atomicAdd(&g_deg[c], __ldg(&ew[e]));
}

// K2: dinv = rsqrt(deg); p = x*dinv; a = p (self-loop contribution)
__global__ void k2_dinv(const float* __restrict__ x) {
    int i = blockIdx.x * blockDim.x + threadIdx.x;
    if (i >= NN) return;
    float d = rsqrtf(g_deg[i]);
    g_dinv[i] = d;
    float p = x[i] * d;
    g_p[i] = p;
    g_a[i] = p;
}

// K3: a[col] += p[row]*ew   (scalar layer-1 scatter)
__global__ void __launch_bounds__(256) k3_scatter1(const int* __restrict__ ei,
                                                   const float* __restrict__ ew) {
    int e = blockIdx.x * blockDim.x + threadIdx.x;
    if (e >= NE) return;
    int r = __ldg(&ei[e]);
    int c = __ldg(&ei[NE + e]);
    atomicAdd(&g_a[c], g_p[r] * __ldg(&ew[e]));
}

// K4: h1 = gelu(a*dinv*W1 + b1); s1 = (h1 @ W2)*dinv; acc = s1 (self loop)
// block: (64 features, 4 nodes)
__global__ void __launch_bounds__(256) k4_layer1(const float* __restrict__ W1,
                                                 const float* __restrict__ b1,
                                                 const float* __restrict__ W2) {
    __shared__ float W2s[NF * NF];
    __shared__ float hbuf[4][NF];
    int f  = threadIdx.x;
    int ny = threadIdx.y;
    int tid = ny * 64 + f;
    #pragma unroll
    for (int i = 0; i < 16; i++) W2s[tid + i * 256] = W2[tid + i * 256];

    int v = blockIdx.x * 4 + ny;   // NN % 4 == 0, no tail
    float ad = g_a[v] * g_dinv[v];
    float h = gelu_t(ad * __ldg(&W1[f]) + __ldg(&b1[f]));
    hbuf[ny][f] = h;
    __syncthreads();

    float t = 0.0f;
    #pragma unroll 8
    for (int k = 0; k < NF; k++) t = fmaf(hbuf[ny][k], W2s[k * NF + f], t);
    float sv = t * g_dinv[v];
    ((float*)g_s)[v * NF + f]   = sv;
    ((float*)g_acc)[v * NF + f] = sv;
}

// K5: wide layer-2 scatter: acc[col] += s[row]*ew  (16 threads/edge, float4 each)
__global__ void __launch_bounds__(256) k5_scatter2(const int* __restrict__ ei,
                                                   const float* __restrict__ ew) {
    int t = blockIdx.x * blockDim.x + threadIdx.x;   // < NE*16
    int e = t >> 4;
    int j = t & 15;
    int r = __ldg(&ei[e]);
    int c = __ldg(&ei[NE + e]);
    float w = __ldg(&ew[e]);
    float4 v = g_s[r * 16 + j];
    v.x *= w; v.y *= w; v.z *= w; v.w *= w;
    red_add_v4(&g_acc[c * 16 + j], v);
}

// K6: h2 = gelu(acc*dinv + b2); pool sums per graph
__global__ void __launch_bounds__(256) k6_pool(const int* __restrict__ batch,
                                               const float* __restrict__ b2) {
    int idx = blockIdx.x * blockDim.x + threadIdx.x;  // < NN*64
    int v = idx >> 6;
    int f = idx & 63;
    float h = gelu_t(((const float*)g_acc)[idx] * g_dinv[v] + __ldg(&b2[f]));
    int g = __ldg(&batch[v]);
    atomicAdd(&g_gsum[g * NF + f], h);
    if (f == 0) atomicAdd(&g_gcnt[g], 1.0f);
}

// K7: final MLP over 256 graphs (one block, 1 thread per graph)
__global__ void __launch_bounds__(256) k7_mlp(const float* __restrict__ fc1W,
                                              const float* __restrict__ fc1b,
                                              const float* __restrict__ fc2W,
                                              const float* __restrict__ fc2b,
                                              float* __restrict__ out) {
    __shared__ float W1s[64 * 32];
    __shared__ float b1s[32];
    __shared__ float W2s[32];
    int g = threadIdx.x;
    #pragma unroll
    for (int i = 0; i < 8; i++) W1s[g + i * 256] = fc1W[g + i * 256];
    if (g < 32) { b1s[g] = fc1b[g]; W2s[g] = fc2W[g]; }
    __syncthreads();

    float cnt = g_gcnt[g];
    float inv = 1.0f / fmaxf(cnt, 1.0f);
    float m[64];
    #pragma unroll
    for (int k = 0; k < 64; k++) m[k] = g_gsum[g * 64 + k] * inv;

    float o = 0.0f;
    #pragma unroll 4
    for (int j = 0; j < 32; j++) {
        float z = b1s[j];
        #pragma unroll 8
        for (int k = 0; k < 64; k++) z = fmaf(m[k], W1s[k * 32 + j], z);
        o = fmaf(gelu_t(z), W2s[j], o);
    }
    out[g] = o + fc2b[0];
}

extern "C" void kernel_launch(void* const* d_in, const int* in_sizes, int n_in,
                              void* d_out, int out_size) {
    const float* x     = (const float*)d_in[0];
    const int*   ei    = (const int*)d_in[1];     // int32! (JAX x64 disabled)
    const float* ew    = (const float*)d_in[2];
    const int*   batch = (const int*)d_in[3];     // int32!
    const float* W1    = (const float*)d_in[4];
    const float* b1    = (const float*)d_in[5];
    const float* W2    = (const float*)d_in[6];
    const float* b2    = (const float*)d_in[7];
    const float* fc1W  = (const float*)d_in[8];
    const float* fc1b  = (const float*)d_in[9];
    const float* fc2W  = (const float*)d_in[10];
    const float* fc2b  = (const float*)d_in[11];
    float* out = (float*)d_out;

    k0_init<<<(NN + 255) / 256, 256>>>();
    k1_deg<<<(NE + 255) / 256, 256>>>(ei, ew);
    k2_dinv<<<(NN + 255) / 256, 256>>>(x);
    k3_scatter1<<<(NE + 255) / 256, 256>>>(ei, ew);
    k4_layer1<<<NN / 4, dim3(64, 4)>>>(W1, b1, W2);
    k5_scatter2<<<(NE * 16) / 256, 256>>>(ei, ew);
    k6_pool<<<(NN * 64) / 256, 256>>>(batch, b2);
    k7_mlp<<<1, 256>>>(fc1W, fc1b, fc2W, fc2b, out);
}